// round 9
// baseline (speedup 1.0000x reference)
#include <cuda_runtime.h>
#include <cuda_bf16.h>

#define BB 4
#define CIN 64
#define CO 128
#define HH 256
#define WW 256
#define HWP 65536
#define NOUT (BB*4*HWP)   // 1048576

typedef unsigned long long u64;

// scratch
__device__ float g_h[(size_t)BB * CO * HWP];                          // conv1 out [b][cout][pix]
__device__ __align__(256) unsigned short g_xh[(size_t)BB * HWP * 64]; // x hi, [b][pix][ci] bf16
__device__ __align__(256) unsigned short g_xl[(size_t)BB * HWP * 64]; // x lo
__device__ __align__(256) unsigned char  g_wp[18 * 16384];            // 9 taps x {hi,lo}, swizzled [cout][ci]

// ---- f32x2 helpers --------------------------------------------------------
__device__ __forceinline__ void fma2(u64& d, u64 a, u64 b) {
    asm("fma.rn.f32x2 %0, %1, %2, %0;" : "+l"(d) : "l"(a), "l"(b));
}
__device__ __forceinline__ u64 dup2(float x) {
    u64 d; asm("mov.b64 %0, {%1, %1};" : "=l"(d) : "f"(x)); return d;
}
__device__ __forceinline__ float2 unpk(u64 d) {
    float2 r; asm("mov.b64 {%0, %1}, %2;" : "=f"(r.x), "=f"(r.y) : "l"(d));
    return r;
}

// ---- fast transcendentals (abs err ~1e-7) ---------------------------------
__device__ __forceinline__ float fast_tanh(float x) {
    float e;
    asm("ex2.approx.f32 %0, %1;" : "=f"(e) : "f"(x * 2.8853900817779268f));
    float r;
    asm("rcp.approx.f32 %0, %1;" : "=f"(r) : "f"(1.0f + e));
    return fmaf(-2.0f, r, 1.0f);
}
__device__ __forceinline__ float fast_sigmoid(float x) {
    float e;
    asm("ex2.approx.f32 %0, %1;" : "=f"(e) : "f"(-x * 1.4426950408889634f));
    float r;
    asm("rcp.approx.f32 %0, %1;" : "=f"(r) : "f"(1.0f + e));
    return r;
}

// ---- cp.async helpers -----------------------------------------------------
__device__ __forceinline__ void cpa16(unsigned saddr, const void* gaddr) {
    asm volatile("cp.async.cg.shared.global [%0], [%1], 16;"
                 :: "r"(saddr), "l"(gaddr));
}
__device__ __forceinline__ void cpa16z(unsigned saddr, const void* gaddr, int ok) {
    asm volatile("cp.async.cg.shared.global [%0], [%1], 16, %2;"
                 :: "r"(saddr), "l"(gaddr), "r"(ok ? 16 : 0));
}
__device__ __forceinline__ void cpa4z(unsigned saddr, const void* gaddr, int pred) {
    asm volatile("cp.async.ca.shared.global [%0], [%1], 4, %2;"
                 :: "r"(saddr), "l"(gaddr), "r"(pred ? 4 : 0));
}
__device__ __forceinline__ void cpa_commit() {
    asm volatile("cp.async.commit_group;");
}
__device__ __forceinline__ void cpa_wait_all() {
    asm volatile("cp.async.wait_group 0;");
}

// ---- legacy tensor core: ldmatrix + mma.sync ------------------------------
__device__ __forceinline__ void ldmx4(unsigned& r0, unsigned& r1,
                                      unsigned& r2, unsigned& r3, unsigned a) {
    asm volatile("ldmatrix.sync.aligned.m8n8.x4.shared.b16 {%0,%1,%2,%3}, [%4];"
                 : "=r"(r0), "=r"(r1), "=r"(r2), "=r"(r3) : "r"(a));
}
__device__ __forceinline__ void mma_bf16(float* d, unsigned a0, unsigned a1,
                                         unsigned a2, unsigned a3,
                                         unsigned b0, unsigned b1) {
    asm volatile(
        "mma.sync.aligned.m16n8k16.row.col.f32.bf16.bf16.f32 "
        "{%0,%1,%2,%3}, {%4,%5,%6,%7}, {%8,%9}, {%0,%1,%2,%3};"
        : "+f"(d[0]), "+f"(d[1]), "+f"(d[2]), "+f"(d[3])
        : "r"(a0), "r"(a1), "r"(a2), "r"(a3), "r"(b0), "r"(b1));
}
__device__ __forceinline__ int swz(int off) { return off ^ ((off >> 3) & 0x70); }

// ---------------------------------------------------------------------------
// Prep 1: split conv weights to bf16 hi/lo, SW128-swizzled [cout][ci] tiles.
// ---------------------------------------------------------------------------
__global__ void wprep(const float* __restrict__ Wc) {
    int i = blockIdx.x * 256 + threadIdx.x;   // < 73728
    int tap = i >> 13, rem = i & 8191, cout = rem >> 6, ci = rem & 63;
    float v = Wc[cout * 576 + ci * 9 + tap];
    __nv_bfloat16 h = __float2bfloat16(v);
    float hf = __bfloat162float(h);
    __nv_bfloat16 l = __float2bfloat16(v - hf);
    int sw = swz(cout * 128 + ci * 2);
    *(unsigned short*)(g_wp + (tap * 2 + 0) * 16384 + sw) =
        *reinterpret_cast<unsigned short*>(&h);
    *(unsigned short*)(g_wp + (tap * 2 + 1) * 16384 + sw) =
        *reinterpret_cast<unsigned short*>(&l);
}

// ---------------------------------------------------------------------------
// Prep 2: transpose x to pixel-major bf16 hi/lo: g_x{h,l}[b][pix][ci]
// ---------------------------------------------------------------------------
__global__ void xprep(const float* __restrict__ x) {
    __shared__ unsigned short shh[32 * 66], shl[32 * 66];
    const int bx = blockIdx.x;
    const int b = bx >> 11;
    const int px0 = (bx & 2047) * 32;
    const int tid = threadIdx.x;
    for (int i = tid; i < 2048; i += 256) {
        int ci = i >> 5, p = i & 31;
        float v = x[(((size_t)b * 64 + ci) << 16) + px0 + p];
        __nv_bfloat16 h = __float2bfloat16(v);
        float hf = __bfloat162float(h);
        __nv_bfloat16 l = __float2bfloat16(v - hf);
        shh[p * 66 + ci] = *reinterpret_cast<unsigned short*>(&h);
        shl[p * 66 + ci] = *reinterpret_cast<unsigned short*>(&l);
    }
    __syncthreads();
    for (int i = tid; i < 1024; i += 256) {
        int p = i >> 5, j = i & 31;
        unsigned vh = shh[p * 66 + 2 * j] | ((unsigned)shh[p * 66 + 2 * j + 1] << 16);
        unsigned vl = shl[p * 66 + 2 * j] | ((unsigned)shl[p * 66 + 2 * j + 1] << 16);
        size_t rb = ((size_t)b * HWP + px0 + p) * 32 + j;
        reinterpret_cast<unsigned*>(g_xh)[rb] = vh;
        reinterpret_cast<unsigned*>(g_xl)[rb] = vl;
    }
}

// ---------------------------------------------------------------------------
// Kernel 1: conv1 via mma.sync bf16 3-pass (unchanged from R8).
// ---------------------------------------------------------------------------
#define SB_BYTES 49920
#define CV_SMEM (2*SB_BYTES + 65536 + 1024)

__global__ __launch_bounds__(256, 1) void conv_hmma(const float* __restrict__ bc) {
    extern __shared__ unsigned char dsm[];
    const int tid = threadIdx.x;
    const int w = tid >> 5, lane = tid & 31;
    const int blk = blockIdx.x;
    const int xh = blk & 1, y = (blk >> 1) & 255, b = blk >> 9;
    const int x0 = xh * 128;

    unsigned raw = (unsigned)__cvta_generic_to_shared(dsm);
    unsigned base = (raw + 1023) & ~1023u;
    unsigned sBh = base, sBl = base + SB_BYTES, sA = base + 2 * SB_BYTES;

    for (int i = tid; i < 6240; i += 256) {
        int half = (i >= 3120);
        int idx = half ? i - 3120 : i;
        int r = idx >> 3, c = idx & 7;
        int ky = r / 130, p = r % 130;
        int gy = y + ky - 1, gx = x0 + p - 1;
        int ok = (gy >= 0 && gy < HH && gx >= 0 && gx < WW);
        const unsigned char* src =
            (half ? (const unsigned char*)g_xl : (const unsigned char*)g_xh)
            + ((size_t)(b * HWP + (ok ? gy * WW + gx : 0)) * 128) + c * 16;
        cpa16z((half ? sBl : sBh) + swz(r * 128 + c * 16), src, ok);
    }
    cpa_commit();

    auto prefA = [&](int t, int buf) {
        const unsigned char* src = g_wp + t * 32768;
        unsigned dst = sA + buf * 32768;
#pragma unroll
        for (int j = 0; j < 8; j++) {
            int off = (tid * 8 + j) * 16;
            cpa16(dst + off, src + off);
        }
        cpa_commit();
    };
    prefA(0, 0);

    const int arow = (16 * w + (lane & 7) + ((lane >> 3) & 1) * 8) * 128
                   + ((lane >> 4) & 1) * 16;
    const int pxl  = (lane & 7) + ((lane >> 4) & 1) * 8;
    const int kextB = ((lane >> 3) & 1) * 16;

    float d[16][4];
#pragma unroll
    for (int j = 0; j < 16; j++)
#pragma unroll
        for (int q = 0; q < 4; q++) d[j][q] = 0.f;

    for (int t = 0; t < 9; t++) {
        cpa_wait_all();
        __syncthreads();
        if (t < 8) prefA(t + 1, (t + 1) & 1);

        const int rowb = (t / 3) * 130 + (t % 3);
        unsigned Ahi = sA + (t & 1) * 32768;
#pragma unroll
        for (int pass = 0; pass < 3; pass++) {
            unsigned Abase = (pass == 2) ? (Ahi + 16384) : Ahi;
            unsigned Bbase = (pass == 1) ? sBl : sBh;
#pragma unroll
            for (int k = 0; k < 4; k++) {
                unsigned a0, a1, a2, a3;
                ldmx4(a0, a1, a2, a3, Abase + swz(arow + k * 32));
                const int bc0 = (rowb + pxl) * 128 + k * 32 + kextB;
#pragma unroll
                for (int jp = 0; jp < 8; jp++) {
                    unsigned b0, b1, b2, b3;
                    ldmx4(b0, b1, b2, b3, Bbase + swz(bc0 + jp * 2048));
                    mma_bf16(d[2 * jp],     a0, a1, a2, a3, b0, b1);
                    mma_bf16(d[2 * jp + 1], a0, a1, a2, a3, b2, b3);
                }
            }
        }
        __syncthreads();
    }

    const int g = lane >> 2, c2 = (lane & 3) * 2;
    const int cout0 = 16 * w + g;
    const float bias0 = bc[cout0], bias1 = bc[cout0 + 8];
    float* h0 = g_h + ((size_t)(b * CO + cout0) << 16) + y * WW + x0 + c2;
    float* h1 = h0 + ((size_t)8 << 16);
#pragma unroll
    for (int j = 0; j < 16; j++) {
        float2 v0 = make_float2(d[j][0] + bias0, d[j][1] + bias0);
        float2 v1 = make_float2(d[j][2] + bias1, d[j][3] + bias1);
        *reinterpret_cast<float2*>(h0 + j * 8) = v0;
        *reinterpret_cast<float2*>(h1 + j * 8) = v1;
    }
}

// ---------------------------------------------------------------------------
// Kernel 2: MC dropout via S/D sparsity. acc[t] = S - sum(dropped channels).
// Block: 128 threads = 128 px of one row; hs[128ch][128px] fp32 in smem.
// ---------------------------------------------------------------------------
__global__ __launch_bounds__(128, 3) void mc_kernel(
    const float* __restrict__ lms, const float* __restrict__ Wo,
    const float* __restrict__ bo, const float* __restrict__ masks,
    float* __restrict__ out)
{
    __shared__ float hs[128 * 128];       // [c][px]  64 KB
    __shared__ float4 sWo[128];           // [c] -> (Wo[0,c],Wo[1,c],Wo[2,c],Wo[3,c])
    __shared__ unsigned char lists[16 * 128];
    __shared__ int cnt[16];

    const int tid = threadIdx.x;
    const int blk = blockIdx.x;           // 2048 = b*512 + y*2 + xh
    const int b = blk >> 9, y = (blk >> 1) & 255, x0 = (blk & 1) * 128;

    // weights per channel (float4 over o)
    {
        float4 v;
        v.x = Wo[0 * 128 + tid];
        v.y = Wo[1 * 128 + tid];
        v.z = Wo[2 * 128 + tid];
        v.w = Wo[3 * 128 + tid];
        sWo[tid] = v;
    }
    // dropped-channel lists (warp-uniform data, threads 0..15)
    if (tid < 16) {
        int n = 0;
        for (int c = 0; c < 128; c++)
            if (masks[tid * 128 + c] == 0.f) lists[tid * 128 + (n++)] = (unsigned char)c;
        cnt[tid] = n;
    }
    // fill hs: thread = channel, 512 B contiguous row segment
    {
        unsigned dst = (unsigned)__cvta_generic_to_shared(&hs[tid * 128]);
        const float* src = g_h + ((size_t)(b * CO + tid) << 16) + y * WW + x0;
#pragma unroll
        for (int j = 0; j < 32; j++)
            cpa16(dst + j * 16, src + j * 4);
        cpa_commit();
    }
    cpa_wait_all();
    __syncthreads();

    // ---- S = full (un-dropped) sum ----
    u64 S01 = 0ull, S23 = 0ull;
#pragma unroll 4
    for (int c = 0; c < 128; c++) {
        float hv = hs[c * 128 + tid];
        ulonglong2 w = *reinterpret_cast<const ulonglong2*>(&sWo[c]);
        u64 hd = dup2(hv);
        fma2(S01, w.x, hd);
        fma2(S23, w.y, hd);
    }

    // ---- D[t] = sum over dropped channels of t ----
    u64 D01[16], D23[16];
#pragma unroll
    for (int t = 0; t < 16; t++) { D01[t] = 0ull; D23[t] = 0ull; }
#pragma unroll
    for (int t = 0; t < 16; t++) {
        const int n = cnt[t];
        const unsigned char* lp = &lists[t * 128];
        for (int i = 0; i < n; i++) {
            int c = lp[i];
            float hv = hs[c * 128 + tid];
            ulonglong2 w = *reinterpret_cast<const ulonglong2*>(&sWo[c]);
            u64 hd = dup2(hv);
            fma2(D01[t], w.x, hd);
            fma2(D23[t], w.y, hd);
        }
    }

    // ---- epilogue: tanh, mean, unbiased var ----
    const int pix = y * WW + x0 + tid;
    float2 s01 = unpk(S01), s23 = unpk(S23);
    float a[16][4];
#pragma unroll
    for (int t = 0; t < 16; t++) {
        float2 d01 = unpk(D01[t]);
        float2 d23 = unpk(D23[t]);
        a[t][0] = s01.x - d01.x; a[t][1] = s01.y - d01.y;
        a[t][2] = s23.x - d23.x; a[t][3] = s23.y - d23.y;
    }
#pragma unroll
    for (int o = 0; o < 4; o++) {
        float bb = bo[o];
        float s[16];
        float sum = 0.f;
#pragma unroll
        for (int t = 0; t < 16; t++) {
            float v = fast_tanh(a[t][o] + bb);
            s[t] = v;
            sum += v;
        }
        float mn = sum * 0.0625f;
        float var = 0.f;
#pragma unroll
        for (int t = 0; t < 16; t++) {
            float dd = s[t] - mn;
            var += dd * dd;
        }
        var *= (1.f / 15.f);
        int oidx = (b * 4 + o) * HWP + pix;
        out[NOUT + oidx]     = var;              // EU
        out[2 * NOUT + oidx] = mn + lms[oidx];   // mean
    }
}

// ---------------------------------------------------------------------------
// Kernel 3: AU conv (R6 pipeline, mc removed). Block 256 = 8x32 px tile.
// ---------------------------------------------------------------------------
#define FILL_N 1360
#define FILL_SLOTS 6

__global__ __launch_bounds__(256, 2) void au_kernel(
    const float* __restrict__ Wa, const float* __restrict__ ba,
    float* __restrict__ out)
{
    __shared__ float sWa[128 * 9 * 4];
    __shared__ float sX[2][4 * 10 * 36];

    const int tid = threadIdx.x;
    for (int i = tid; i < 128 * 36; i += 256) {
        int ci = i / 36, rem = i % 36, k = rem >> 2, o = rem & 3;
        sWa[i] = Wa[(o * 128 + ci) * 9 + k];
    }

    const int b  = blockIdx.z;
    const int y0 = blockIdx.y * 8;
    const int x0 = blockIdx.x * 32;
    const int row = tid >> 5;
    const int col = tid & 31;

    int smoff[FILL_SLOTS]; int goff[FILL_SLOTS]; int gok[FILL_SLOTS];
#pragma unroll
    for (int s = 0; s < FILL_SLOTS; s++) {
        int i = tid + s * 256;
        smoff[s] = -1; goff[s] = 0; gok[s] = 0;
        if (i < FILL_N) {
            int ci = i / 340, r = (i / 34) % 10, c = i % 34;
            int gy = y0 - 1 + r, gx = x0 - 1 + c;
            smoff[s] = (ci * 10 + r) * 36 + c;
            if (gy >= 0 && gy < HH && gx >= 0 && gx < WW) {
                gok[s] = 1;
                goff[s] = ((b * CO + ci) * HH + gy) * WW + gx;
            }
        }
    }

    unsigned sXb[2];
    sXb[0] = (unsigned)__cvta_generic_to_shared(&sX[0][0]);
    sXb[1] = (unsigned)__cvta_generic_to_shared(&sX[1][0]);

    auto prefetch = [&](int cc, int bf) {
        const float* hsrc = g_h + (size_t)cc * 4 * HWP;
#pragma unroll
        for (int s = 0; s < FILL_SLOTS; s++) {
            if (smoff[s] >= 0)
                cpa4z(sXb[bf] + smoff[s] * 4, hsrc + goff[s], gok[s]);
        }
        cpa_commit();
    };

    u64 auA = 0ull, auB = 0ull;

    prefetch(0, 0);
    __syncthreads();

    for (int cc = 0; cc < 32; cc++) {
        const int bf = cc & 1;
        cpa_wait_all();
        __syncthreads();
        if (cc < 31) prefetch(cc + 1, bf ^ 1);

        const float* sXc = &sX[bf][0];
#pragma unroll
        for (int ci = 0; ci < 4; ci++) {
#pragma unroll
            for (int ky = 0; ky < 3; ky++) {
                const float* xr = &sXc[(ci * 10 + row + ky) * 36 + col];
                float v0 = xr[0], v1 = xr[1], v2 = xr[2];
                const ulonglong2* wk = reinterpret_cast<const ulonglong2*>(
                    &sWa[((cc * 4 + ci) * 9 + ky * 3) * 4]);
                ulonglong2 w0 = wk[0], w1 = wk[1], w2 = wk[2];
                u64 x0d = dup2(v0), x1d = dup2(v1), x2d = dup2(v2);
                fma2(auA, w0.x, x0d); fma2(auB, w0.y, x0d);
                fma2(auA, w1.x, x1d); fma2(auB, w1.y, x1d);
                fma2(auA, w2.x, x2d); fma2(auB, w2.y, x2d);
            }
        }
        __syncthreads();
    }

    const int pix = (y0 + row) * WW + x0 + col;
    float2 f01 = unpk(auA);
    float2 f23 = unpk(auB);
    float av[4] = { f01.x, f01.y, f23.x, f23.y };
#pragma unroll
    for (int o = 0; o < 4; o++)
        out[(b * 4 + o) * HWP + pix] = fast_sigmoid(av[o] + ba[o]);
}

// ---------------------------------------------------------------------------
extern "C" void kernel_launch(void* const* d_in, const int* in_sizes, int n_in,
                              void* d_out, int out_size) {
    const float* x     = (const float*)d_in[0];
    const float* lms   = (const float*)d_in[1];
    const float* Wc    = (const float*)d_in[2];
    const float* bc    = (const float*)d_in[3];
    const float* Wo    = (const float*)d_in[4];
    const float* bo    = (const float*)d_in[5];
    const float* Wa    = (const float*)d_in[6];
    const float* ba    = (const float*)d_in[7];
    const float* masks = (const float*)d_in[8];
    float* out = (float*)d_out;

    cudaFuncSetAttribute(conv_hmma,
                         cudaFuncAttributeMaxDynamicSharedMemorySize, CV_SMEM);

    wprep<<<288, 256>>>(Wc);
    xprep<<<8192, 256>>>(x);
    conv_hmma<<<2048, 256, CV_SMEM>>>(bc);
    mc_kernel<<<2048, 128>>>(lms, Wo, bo, masks, out);
    au_kernel<<<dim3(8, 32, 4), 256>>>(Wa, ba, out);
}